// round 7
// baseline (speedup 1.0000x reference)
#include <cuda_runtime.h>
#include <cuda_fp16.h>
#include <cstdint>

// Shapes (fixed)
constexpr int N_  = 128;
constexpr int L_  = 256;
constexpr int DM  = 256;
constexpr int DP  = 128;

// Device scratch (fp16)
__device__ __half g_A[8192 * 128];   // [(l*32+i)][s]
__device__ __half g_B[8192 * 128];   // [(m*32+j)][s]
__device__ __half g_Wt[DP * 1024];   // [n][ij]

// ---------------------------------------------------------------------------
// helpers
// ---------------------------------------------------------------------------
__device__ __forceinline__ uint32_t smem_u32(const void* p) {
    uint32_t a;
    asm("{ .reg .u64 t; cvta.to.shared.u64 t, %1; cvt.u32.u64 %0, t; }"
        : "=r"(a) : "l"(p));
    return a;
}
__device__ __forceinline__ void ldsm4(uint32_t& r0, uint32_t& r1,
                                      uint32_t& r2, uint32_t& r3, uint32_t a) {
    asm volatile("ldmatrix.sync.aligned.m8n8.x4.shared.b16 {%0,%1,%2,%3}, [%4];"
                 : "=r"(r0), "=r"(r1), "=r"(r2), "=r"(r3) : "r"(a));
}
__device__ __forceinline__ void mma16816(float* d, const uint32_t* a,
                                         uint32_t b0, uint32_t b1) {
    asm volatile(
        "mma.sync.aligned.m16n8k16.row.col.f32.f16.f16.f32 "
        "{%0,%1,%2,%3}, {%4,%5,%6,%7}, {%8,%9}, {%0,%1,%2,%3};"
        : "+f"(d[0]), "+f"(d[1]), "+f"(d[2]), "+f"(d[3])
        : "r"(a[0]), "r"(a[1]), "r"(a[2]), "r"(a[3]), "r"(b0), "r"(b1));
}
__device__ __forceinline__ void cpa16(uint32_t dst, const void* src) {
    asm volatile("cp.async.cg.shared.global [%0], [%1], 16;"
                 :: "r"(dst), "l"(src) : "memory");
}
__device__ __forceinline__ void cpa_commit() {
    asm volatile("cp.async.commit_group;" ::: "memory");
}
template <int N>
__device__ __forceinline__ void cpa_wait() {
    asm volatile("cp.async.wait_group %0;" :: "n"(N) : "memory");
}
__device__ __forceinline__ uint32_t pack2h(float a, float b) {
    __half2 h = __floats2half2_rn(a, b);
    return *(uint32_t*)&h;
}

// ---------------------------------------------------------------------------
// Kernel 1: LN + projections via tensor cores (unchanged from round 6).
// ---------------------------------------------------------------------------
constexpr int XST = 264;

__global__ void __launch_bounds__(256) ln_proj_kernel(
    const float* __restrict__ msa,
    const float* __restrict__ gamma,
    const float* __restrict__ beta,
    const float* __restrict__ wl,
    const float* __restrict__ bleft,
    const float* __restrict__ wr,
    const float* __restrict__ bright)
{
    extern __shared__ __half sh[];
    __half* Xs = sh;                    // [128][264]
    __half* Wt = sh + 128 * XST;        // [64][264]
    float*  Osm = (float*)sh;           // reuse X region: [64][132]

    int tid = threadIdx.x, lane = tid & 31, w = tid >> 5;
    int l = blockIdx.x;

    for (int e = tid; e < 8192; e += 256) {
        int d = e >> 5, h = e & 31;
        Wt[h * XST + d]        = __float2half_rn(wl[e]);
        Wt[(h + 32) * XST + d] = __float2half_rn(wr[e]);
    }

    float4 ga0 = *(const float4*)&gamma[lane * 8];
    float4 ga1 = *(const float4*)&gamma[lane * 8 + 4];
    float4 be0 = *(const float4*)&beta[lane * 8];
    float4 be1 = *(const float4*)&beta[lane * 8 + 4];

#pragma unroll 2
    for (int rr = 0; rr < 16; rr++) {
        int s = w * 16 + rr;
        const float* x = msa + ((size_t)s * L_ + l) * DM;
        float4 x0 = *(const float4*)&x[lane * 8];
        float4 x1 = *(const float4*)&x[lane * 8 + 4];
        float sum = x0.x + x0.y + x0.z + x0.w + x1.x + x1.y + x1.z + x1.w;
        float sq  = x0.x*x0.x + x0.y*x0.y + x0.z*x0.z + x0.w*x0.w
                  + x1.x*x1.x + x1.y*x1.y + x1.z*x1.z + x1.w*x1.w;
#pragma unroll
        for (int o = 16; o > 0; o >>= 1) {
            sum += __shfl_xor_sync(0xffffffffu, sum, o);
            sq  += __shfl_xor_sync(0xffffffffu, sq,  o);
        }
        float mu = sum * (1.f / DM);
        float rstd = rsqrtf(sq * (1.f / DM) - mu * mu + 1e-5f);
        uint4 pk;
        pk.x = pack2h((x0.x - mu) * rstd * ga0.x + be0.x,
                      (x0.y - mu) * rstd * ga0.y + be0.y);
        pk.y = pack2h((x0.z - mu) * rstd * ga0.z + be0.z,
                      (x0.w - mu) * rstd * ga0.w + be0.w);
        pk.z = pack2h((x1.x - mu) * rstd * ga1.x + be1.x,
                      (x1.y - mu) * rstd * ga1.y + be1.y);
        pk.w = pack2h((x1.z - mu) * rstd * ga1.z + be1.z,
                      (x1.w - mu) * rstd * ga1.w + be1.w);
        *(uint4*)&Xs[s * XST + lane * 8] = pk;
    }
    __syncthreads();

    int wm = w >> 1, wn = w & 1;
    float acc[2][4][4];
#pragma unroll
    for (int mt = 0; mt < 2; mt++)
#pragma unroll
        for (int nt = 0; nt < 4; nt++)
#pragma unroll
            for (int q = 0; q < 4; q++) acc[mt][nt][q] = 0.f;

    uint32_t sb = smem_u32(sh);
    uint32_t aAddr = sb + (uint32_t)(((wm * 32 + (lane & 15)) * XST + (lane >> 4) * 8) * 2);
    uint32_t bAddr = sb + (uint32_t)((128 * XST
                    + (wn * 32 + ((lane >> 4) & 1) * 8 + (lane & 7)) * XST
                    + ((lane >> 3) & 1) * 8) * 2);

#pragma unroll
    for (int ks = 0; ks < 16; ks++) {
        uint32_t a[2][4], b[2][4];
#pragma unroll
        for (int mt = 0; mt < 2; mt++)
            ldsm4(a[mt][0], a[mt][1], a[mt][2], a[mt][3],
                  aAddr + (uint32_t)((mt * 16 * XST + ks * 16) * 2));
#pragma unroll
        for (int n2 = 0; n2 < 2; n2++)
            ldsm4(b[n2][0], b[n2][1], b[n2][2], b[n2][3],
                  bAddr + (uint32_t)((n2 * 16 * XST + ks * 16) * 2));
#pragma unroll
        for (int mt = 0; mt < 2; mt++)
#pragma unroll
            for (int nt = 0; nt < 4; nt++)
                mma16816(acc[mt][nt], a[mt],
                         b[nt >> 1][(nt & 1) * 2], b[nt >> 1][(nt & 1) * 2 + 1]);
    }
    __syncthreads();

    {
        int rB = lane >> 2, cB = (lane & 3) * 2;
#pragma unroll
        for (int mt = 0; mt < 2; mt++) {
            int r = wm * 32 + mt * 16 + rB;
#pragma unroll
            for (int nt = 0; nt < 4; nt++) {
                int c = wn * 32 + nt * 8 + cB;
                Osm[c * 132 + r]            = acc[mt][nt][0];
                Osm[(c + 1) * 132 + r]      = acc[mt][nt][1];
                Osm[c * 132 + r + 8]        = acc[mt][nt][2];
                Osm[(c + 1) * 132 + r + 8]  = acc[mt][nt][3];
            }
        }
    }
    __syncthreads();

    {
        int n = tid >> 2, s0 = (tid & 3) * 32;
        bool isL = n < 32;
        int hh = isL ? n : n - 32;
        float bias = isL ? bleft[hh] : bright[hh];
        float scale = isL ? 1.f : (1.f / 128.f);
        __half* dst = (isL ? g_A : g_B) + (size_t)(l * 32 + hh) * 128 + s0;
#pragma unroll
        for (int q = 0; q < 4; q++) {
            float4 v0 = *(float4*)&Osm[n * 132 + s0 + q * 8];
            float4 v1 = *(float4*)&Osm[n * 132 + s0 + q * 8 + 4];
            uint4 pk;
            pk.x = pack2h((v0.x + bias) * scale, (v0.y + bias) * scale);
            pk.y = pack2h((v0.z + bias) * scale, (v0.w + bias) * scale);
            pk.z = pack2h((v1.x + bias) * scale, (v1.y + bias) * scale);
            pk.w = pack2h((v1.z + bias) * scale, (v1.w + bias) * scale);
            *(uint4*)(dst + q * 8) = pk;
        }
    }
}

// ---------------------------------------------------------------------------
// w_out transpose to fp16: g_Wt[n][ij]
// ---------------------------------------------------------------------------
__global__ void __launch_bounds__(256) wt_kernel(const float* __restrict__ wo)
{
    int idx = blockIdx.x * 256 + threadIdx.x;
    int k = idx >> 7, n = idx & 127;
    g_Wt[(size_t)n * 1024 + k] = __float2half_rn(wo[idx]);
}

// ---------------------------------------------------------------------------
// Fused GEMM, fp16 MMA. CTA = 8 l x 4 m = 32 pairs; 2 CTAs/SM.
//   B tile 128 rows resident; A double-buffered; W in 16 half-chunks (64 K),
//   double-buffered, one cp.async group per half-chunk.
// ---------------------------------------------------------------------------
constexpr int STH   = 136;                      // halves
constexpr int WKST  = 72;                       // W sub stride (halves)
constexpr int B_OFF = 0;                        // [128][136]
constexpr int A_OFF = 128 * STH;                // 2 x [32][136]
constexpr int G_OFF = A_OFF + 2 * 32 * STH;     // [32][136]
constexpr int W_OFF = G_OFF + 32 * STH;         // 2 x [128][72]
constexpr int ABUF  = 32 * STH;
constexpr int WBUF  = 128 * WKST;
constexpr int SMEM_FUSED = (W_OFF + 2 * WBUF) * 2;   // 97792 bytes

__global__ void __launch_bounds__(256, 2) fused_gemm_kernel(
    const float* __restrict__ pairin,
    const float* __restrict__ bo,
    float* __restrict__ outp)
{
    extern __shared__ __half smh[];
    float* smf = (float*)smh;
    uint32_t sb = smem_u32(smh);
    int tid = threadIdx.x, lane = tid & 31, w = tid >> 5;
    int bl = blockIdx.x, bm = blockIdx.y;

    const __half* gA = g_A + (size_t)(bl * 256) * 128;   // 8 l * 32 i rows
    const __half* gB = g_B + (size_t)(bm * 128) * 128;   // 4 m * 32 j rows

    auto prefetchW = [&](int t) {   // half-chunk t (64 k) -> slot t&1
        uint32_t base = sb + (uint32_t)((W_OFF + (t & 1) * WBUF) * 2);
        int row = tid >> 1;
        int sg0 = (tid & 1) * 4;
        const __half* src = g_Wt + (size_t)row * 1024 + t * 64;
        uint32_t dst = base + (uint32_t)(row * WKST * 2);
#pragma unroll
        for (int q = 0; q < 4; q++)
            cpa16(dst + (sg0 + q) * 16, src + (sg0 + q) * 8);
    };
    auto prefetchA = [&](int c) {   // A chunk c -> slot c&1
        uint32_t base = sb + (uint32_t)((A_OFF + (c & 1) * ABUF) * 2);
#pragma unroll
        for (int it = 0; it < 2; it++) {
            int f = it * 256 + tid;
            int r = f >> 4, c8 = (f & 15) * 8;
            int grow = (r >> 2) * 32 + c * 4 + (r & 3);
            cpa16(base + (uint32_t)((r * STH + c8) * 2),
                  gA + (size_t)grow * 128 + c8);
        }
    };

    // prologue group: B (128 rows) + A[0] + W[0]
#pragma unroll
    for (int it = 0; it < 8; it++) {
        int f = it * 256 + tid;
        int r = f >> 4, c8 = (f & 15) * 8;
        cpa16(sb + (uint32_t)((B_OFF + r * STH + c8) * 2),
              gB + (size_t)r * 128 + c8);
    }
    prefetchA(0);
    prefetchW(0);
    cpa_commit();

    float outAcc[2][2][4];
#pragma unroll
    for (int mt = 0; mt < 2; mt++)
#pragma unroll
        for (int nt = 0; nt < 2; nt++)
#pragma unroll
            for (int q = 0; q < 4; q++) outAcc[mt][nt][q] = 0.f;

    // ldmatrix bases
    uint32_t aAddrA0 = sb + (uint32_t)((A_OFF + (lane & 15) * STH + (lane >> 4) * 8) * 2);
    uint32_t bAddrA  = sb + (uint32_t)((B_OFF + (w * 16 + ((lane >> 4) & 1) * 8 + (lane & 7)) * STH
                                        + ((lane >> 3) & 1) * 8) * 2);
    uint32_t aAddrB  = sb + (uint32_t)((G_OFF + (lane & 15) * STH + (lane >> 4) * 8) * 2);
    uint32_t bAddrW0 = (uint32_t)((W_OFF + (w * 16 + ((lane >> 4) & 1) * 8 + (lane & 7)) * WKST
                                   + ((lane >> 3) & 1) * 8) * 2);

#pragma unroll 1
    for (int t = 0; t < 16; t++) {
        int ic = t >> 1, wsub = t & 1;
        __syncthreads();                 // prior readers of slot (t+1)&1 / Gs done
        if (t + 1 < 16) {
            prefetchW(t + 1);
            if (wsub == 1) prefetchA(ic + 1);
            cpa_commit();
            cpa_wait<1>();               // W[t] (+A[ic], B first iter) arrived
        } else {
            cpa_wait<0>();
        }
        __syncthreads();                 // visible to all warps

        if (wsub == 0) {
            // ---- phase A: Gc[32 x 128] = A[32 x 128s] @ B^T ----
            uint32_t aA = aAddrA0 + (uint32_t)((ic & 1) * ABUF * 2);
            float accA[2][2][4];
#pragma unroll
            for (int mt = 0; mt < 2; mt++)
#pragma unroll
                for (int nt = 0; nt < 2; nt++)
#pragma unroll
                    for (int q = 0; q < 4; q++) accA[mt][nt][q] = 0.f;

#pragma unroll
            for (int ks = 0; ks < 8; ks++) {
                uint32_t a[2][4], b[4];
#pragma unroll
                for (int mt = 0; mt < 2; mt++)
                    ldsm4(a[mt][0], a[mt][1], a[mt][2], a[mt][3],
                          aA + (uint32_t)((mt * 16 * STH + ks * 16) * 2));
                ldsm4(b[0], b[1], b[2], b[3],
                      bAddrA + (uint32_t)((ks * 16) * 2));
#pragma unroll
                for (int mt = 0; mt < 2; mt++) {
                    mma16816(accA[mt][0], a[mt], b[0], b[1]);
                    mma16816(accA[mt][1], a[mt], b[2], b[3]);
                }
            }

            // ---- store Gc -> Gs[pair][ij_local] fp16 ----
            int rB = lane >> 2, jB = (lane & 3) * 2;
#pragma unroll
            for (int mt = 0; mt < 2; mt++) {
#pragma unroll
                for (int nt = 0; nt < 2; nt++) {
                    int col = w * 16 + nt * 8 + jB;
                    int mloc = col >> 5, j = col & 31;
                    int r0 = mt * 16 + rB;
                    int p0 = (r0 >> 2) * 4 + mloc;
                    int q0 = (r0 & 3) * 32 + j;
                    *(uint32_t*)(smh + G_OFF + p0 * STH + q0) =
                        pack2h(accA[mt][nt][0], accA[mt][nt][1]);
                    int r1 = r0 + 8;
                    int p1 = (r1 >> 2) * 4 + mloc;
                    int q1 = (r1 & 3) * 32 + j;
                    *(uint32_t*)(smh + G_OFF + p1 * STH + q1) =
                        pack2h(accA[mt][nt][2], accA[mt][nt][3]);
                }
            }
            __syncthreads();             // Gs visible
        }

        // ---- phase B: out += Gs[32 x 64k] @ Wsub[128n x 64k]^T ----
        uint32_t aB = aAddrB + (uint32_t)((wsub * 64) * 2);
        uint32_t sW = sb + bAddrW0 + (uint32_t)((t & 1) * WBUF * 2);
#pragma unroll
        for (int ks = 0; ks < 4; ks++) {
            uint32_t a[2][4], b[4];
#pragma unroll
            for (int mt = 0; mt < 2; mt++)
                ldsm4(a[mt][0], a[mt][1], a[mt][2], a[mt][3],
                      aB + (uint32_t)((mt * 16 * STH + ks * 16) * 2));
            ldsm4(b[0], b[1], b[2], b[3], sW + (uint32_t)((ks * 16) * 2));
#pragma unroll
            for (int mt = 0; mt < 2; mt++) {
                mma16816(outAcc[mt][0], a[mt], b[0], b[1]);
                mma16816(outAcc[mt][1], a[mt], b[2], b[3]);
            }
        }
    }
    __syncthreads();

    // ---- epilogue: stage f32 in B region (stride 132), coalesced writes ----
    {
        int rB = lane >> 2, nB = (lane & 3) * 2;
#pragma unroll
        for (int mt = 0; mt < 2; mt++) {
            int p = mt * 16 + rB;
#pragma unroll
            for (int nt = 0; nt < 2; nt++) {
                int nc = w * 16 + nt * 8 + nB;
                *(float2*)&smf[p * 132 + nc] =
                    make_float2(outAcc[mt][nt][0], outAcc[mt][nt][1]);
                *(float2*)&smf[(p + 8) * 132 + nc] =
                    make_float2(outAcc[mt][nt][2], outAcc[mt][nt][3]);
            }
        }
    }
    __syncthreads();

#pragma unroll
    for (int it = 0; it < 4; it++) {
        int f = it * 256 + tid;          // 1024 float4
        int p = f >> 5;                  // pair 0..31
        int c4 = (f & 31) * 4;
        int l = bl * 8 + (p >> 2);
        int m = bm * 4 + (p & 3);
        size_t o = ((size_t)(l * L_ + m)) * DP + c4;
        float4 v = *(float4*)&smf[p * 132 + c4];
        float4 pv = *(const float4*)&pairin[o];
        float4 bv = *(const float4*)&bo[c4];
        v.x += pv.x + bv.x; v.y += pv.y + bv.y;
        v.z += pv.z + bv.z; v.w += pv.w + bv.w;
        *(float4*)&outp[o] = v;
    }
}

// ---------------------------------------------------------------------------
// Launch
// ---------------------------------------------------------------------------
extern "C" void kernel_launch(void* const* d_in, const int* in_sizes, int n_in,
                              void* d_out, int out_size)
{
    const float* msa    = (const float*)d_in[0];
    const float* pairin = (const float*)d_in[1];
    const float* gamma  = (const float*)d_in[4];
    const float* beta   = (const float*)d_in[5];
    const float* wl     = (const float*)d_in[6];
    const float* bleft  = (const float*)d_in[7];
    const float* wr     = (const float*)d_in[8];
    const float* bright = (const float*)d_in[9];
    const float* wo     = (const float*)d_in[10];
    const float* bo     = (const float*)d_in[11];
    float* outp = (float*)d_out;

    int smemLn = 192 * XST * 2;
    cudaFuncSetAttribute(ln_proj_kernel,
                         cudaFuncAttributeMaxDynamicSharedMemorySize, smemLn);
    cudaFuncSetAttribute(fused_gemm_kernel,
                         cudaFuncAttributeMaxDynamicSharedMemorySize, SMEM_FUSED);

    ln_proj_kernel<<<256, 256, smemLn>>>(msa, gamma, beta, wl, bleft, wr, bright);
    wt_kernel<<<512, 256>>>(wo);
    fused_gemm_kernel<<<dim3(32, 64), 256, SMEM_FUSED>>>(pairin, bo, outp);
}

// round 8
// speedup vs baseline: 1.0826x; 1.0826x over previous
#include <cuda_runtime.h>
#include <cuda_fp16.h>
#include <cstdint>

// Shapes (fixed)
constexpr int N_  = 128;
constexpr int L_  = 256;
constexpr int DM  = 256;
constexpr int DP  = 128;

// Device scratch (fp16)
__device__ __half g_A[8192 * 128];   // [(l*32+i)][s]
__device__ __half g_B[8192 * 128];   // [(m*32+j)][s]
__device__ __half g_Wt[DP * 1024];   // [n][ij]

// ---------------------------------------------------------------------------
// helpers
// ---------------------------------------------------------------------------
__device__ __forceinline__ uint32_t smem_u32(const void* p) {
    uint32_t a;
    asm("{ .reg .u64 t; cvta.to.shared.u64 t, %1; cvt.u32.u64 %0, t; }"
        : "=r"(a) : "l"(p));
    return a;
}
__device__ __forceinline__ void ldsm4(uint32_t& r0, uint32_t& r1,
                                      uint32_t& r2, uint32_t& r3, uint32_t a) {
    asm volatile("ldmatrix.sync.aligned.m8n8.x4.shared.b16 {%0,%1,%2,%3}, [%4];"
                 : "=r"(r0), "=r"(r1), "=r"(r2), "=r"(r3) : "r"(a));
}
__device__ __forceinline__ void mma16816(float* d, const uint32_t* a,
                                         uint32_t b0, uint32_t b1) {
    asm volatile(
        "mma.sync.aligned.m16n8k16.row.col.f32.f16.f16.f32 "
        "{%0,%1,%2,%3}, {%4,%5,%6,%7}, {%8,%9}, {%0,%1,%2,%3};"
        : "+f"(d[0]), "+f"(d[1]), "+f"(d[2]), "+f"(d[3])
        : "r"(a[0]), "r"(a[1]), "r"(a[2]), "r"(a[3]), "r"(b0), "r"(b1));
}
__device__ __forceinline__ void cpa16(uint32_t dst, const void* src) {
    asm volatile("cp.async.cg.shared.global [%0], [%1], 16;"
                 :: "r"(dst), "l"(src) : "memory");
}
__device__ __forceinline__ void cpa_commit() {
    asm volatile("cp.async.commit_group;" ::: "memory");
}
template <int N>
__device__ __forceinline__ void cpa_wait() {
    asm volatile("cp.async.wait_group %0;" :: "n"(N) : "memory");
}
__device__ __forceinline__ uint32_t pack2h(float a, float b) {
    __half2 h = __floats2half2_rn(a, b);
    return *(uint32_t*)&h;
}

// ---------------------------------------------------------------------------
// Kernel 1: LN + projections via tensor cores (round-6 version).
// ---------------------------------------------------------------------------
constexpr int XST = 264;

__global__ void __launch_bounds__(256) ln_proj_kernel(
    const float* __restrict__ msa,
    const float* __restrict__ gamma,
    const float* __restrict__ beta,
    const float* __restrict__ wl,
    const float* __restrict__ bleft,
    const float* __restrict__ wr,
    const float* __restrict__ bright)
{
    extern __shared__ __half sh[];
    __half* Xs = sh;                    // [128][264]
    __half* Wt = sh + 128 * XST;        // [64][264]
    float*  Osm = (float*)sh;           // reuse X region: [64][132]

    int tid = threadIdx.x, lane = tid & 31, w = tid >> 5;
    int l = blockIdx.x;

    for (int e = tid; e < 8192; e += 256) {
        int d = e >> 5, h = e & 31;
        Wt[h * XST + d]        = __float2half_rn(wl[e]);
        Wt[(h + 32) * XST + d] = __float2half_rn(wr[e]);
    }

    float4 ga0 = *(const float4*)&gamma[lane * 8];
    float4 ga1 = *(const float4*)&gamma[lane * 8 + 4];
    float4 be0 = *(const float4*)&beta[lane * 8];
    float4 be1 = *(const float4*)&beta[lane * 8 + 4];

#pragma unroll 2
    for (int rr = 0; rr < 16; rr++) {
        int s = w * 16 + rr;
        const float* x = msa + ((size_t)s * L_ + l) * DM;
        float4 x0 = *(const float4*)&x[lane * 8];
        float4 x1 = *(const float4*)&x[lane * 8 + 4];
        float sum = x0.x + x0.y + x0.z + x0.w + x1.x + x1.y + x1.z + x1.w;
        float sq  = x0.x*x0.x + x0.y*x0.y + x0.z*x0.z + x0.w*x0.w
                  + x1.x*x1.x + x1.y*x1.y + x1.z*x1.z + x1.w*x1.w;
#pragma unroll
        for (int o = 16; o > 0; o >>= 1) {
            sum += __shfl_xor_sync(0xffffffffu, sum, o);
            sq  += __shfl_xor_sync(0xffffffffu, sq,  o);
        }
        float mu = sum * (1.f / DM);
        float rstd = rsqrtf(sq * (1.f / DM) - mu * mu + 1e-5f);
        uint4 pk;
        pk.x = pack2h((x0.x - mu) * rstd * ga0.x + be0.x,
                      (x0.y - mu) * rstd * ga0.y + be0.y);
        pk.y = pack2h((x0.z - mu) * rstd * ga0.z + be0.z,
                      (x0.w - mu) * rstd * ga0.w + be0.w);
        pk.z = pack2h((x1.x - mu) * rstd * ga1.x + be1.x,
                      (x1.y - mu) * rstd * ga1.y + be1.y);
        pk.w = pack2h((x1.z - mu) * rstd * ga1.z + be1.z,
                      (x1.w - mu) * rstd * ga1.w + be1.w);
        *(uint4*)&Xs[s * XST + lane * 8] = pk;
    }
    __syncthreads();

    int wm = w >> 1, wn = w & 1;
    float acc[2][4][4];
#pragma unroll
    for (int mt = 0; mt < 2; mt++)
#pragma unroll
        for (int nt = 0; nt < 4; nt++)
#pragma unroll
            for (int q = 0; q < 4; q++) acc[mt][nt][q] = 0.f;

    uint32_t sb = smem_u32(sh);
    uint32_t aAddr = sb + (uint32_t)(((wm * 32 + (lane & 15)) * XST + (lane >> 4) * 8) * 2);
    uint32_t bAddr = sb + (uint32_t)((128 * XST
                    + (wn * 32 + ((lane >> 4) & 1) * 8 + (lane & 7)) * XST
                    + ((lane >> 3) & 1) * 8) * 2);

#pragma unroll
    for (int ks = 0; ks < 16; ks++) {
        uint32_t a[2][4], b[2][4];
#pragma unroll
        for (int mt = 0; mt < 2; mt++)
            ldsm4(a[mt][0], a[mt][1], a[mt][2], a[mt][3],
                  aAddr + (uint32_t)((mt * 16 * XST + ks * 16) * 2));
#pragma unroll
        for (int n2 = 0; n2 < 2; n2++)
            ldsm4(b[n2][0], b[n2][1], b[n2][2], b[n2][3],
                  bAddr + (uint32_t)((n2 * 16 * XST + ks * 16) * 2));
#pragma unroll
        for (int mt = 0; mt < 2; mt++)
#pragma unroll
            for (int nt = 0; nt < 4; nt++)
                mma16816(acc[mt][nt], a[mt],
                         b[nt >> 1][(nt & 1) * 2], b[nt >> 1][(nt & 1) * 2 + 1]);
    }
    __syncthreads();

    {
        int rB = lane >> 2, cB = (lane & 3) * 2;
#pragma unroll
        for (int mt = 0; mt < 2; mt++) {
            int r = wm * 32 + mt * 16 + rB;
#pragma unroll
            for (int nt = 0; nt < 4; nt++) {
                int c = wn * 32 + nt * 8 + cB;
                Osm[c * 132 + r]            = acc[mt][nt][0];
                Osm[(c + 1) * 132 + r]      = acc[mt][nt][1];
                Osm[c * 132 + r + 8]        = acc[mt][nt][2];
                Osm[(c + 1) * 132 + r + 8]  = acc[mt][nt][3];
            }
        }
    }
    __syncthreads();

    {
        int n = tid >> 2, s0 = (tid & 3) * 32;
        bool isL = n < 32;
        int hh = isL ? n : n - 32;
        float bias = isL ? bleft[hh] : bright[hh];
        float scale = isL ? 1.f : (1.f / 128.f);
        __half* dst = (isL ? g_A : g_B) + (size_t)(l * 32 + hh) * 128 + s0;
#pragma unroll
        for (int q = 0; q < 4; q++) {
            float4 v0 = *(float4*)&Osm[n * 132 + s0 + q * 8];
            float4 v1 = *(float4*)&Osm[n * 132 + s0 + q * 8 + 4];
            uint4 pk;
            pk.x = pack2h((v0.x + bias) * scale, (v0.y + bias) * scale);
            pk.y = pack2h((v0.z + bias) * scale, (v0.w + bias) * scale);
            pk.z = pack2h((v1.x + bias) * scale, (v1.y + bias) * scale);
            pk.w = pack2h((v1.z + bias) * scale, (v1.w + bias) * scale);
            *(uint4*)(dst + q * 8) = pk;
        }
    }
}

// ---------------------------------------------------------------------------
// w_out transpose to fp16: g_Wt[n][ij]
// ---------------------------------------------------------------------------
__global__ void __launch_bounds__(256) wt_kernel(const float* __restrict__ wo)
{
    int idx = blockIdx.x * 256 + threadIdx.x;
    int k = idx >> 7, n = idx & 127;
    g_Wt[(size_t)n * 1024 + k] = __float2half_rn(wo[idx]);
}

// ---------------------------------------------------------------------------
// Fused GEMM, fp16 MMA. CTA = 8 l x 8 m = 64 pairs, grid 32x32.
//   A + B fully resident in SMEM; W double-buffered full 128-K chunks;
//   ldsm register double-buffering in both phase loops.
// ---------------------------------------------------------------------------
constexpr int STH   = 136;                      // halves
constexpr int B_OFF = 0;                        // [256][136]
constexpr int A_OFF = 256 * STH;                // [256][136]
constexpr int G_OFF = A_OFF + 256 * STH;        // [64][136]
constexpr int W_OFF = G_OFF + 64 * STH;         // 2 x [128][136]
constexpr int WBUF  = 128 * STH;
constexpr int SMEM_FUSED = (W_OFF + 2 * WBUF) * 2;   // 226304 bytes

__global__ void __launch_bounds__(256, 1) fused_gemm_kernel(
    const float* __restrict__ pairin,
    const float* __restrict__ bo,
    float* __restrict__ outp)
{
    extern __shared__ __half smh[];
    float* smf = (float*)smh;
    uint32_t sb = smem_u32(smh);
    int tid = threadIdx.x, lane = tid & 31, w = tid >> 5;
    int bl = blockIdx.x, bm = blockIdx.y;

    const __half* gA = g_A + (size_t)(bl * 256) * 128;
    const __half* gB = g_B + (size_t)(bm * 256) * 128;

    auto prefetchW = [&](int c) {   // W chunk c -> slot c&1
        uint32_t base = sb + (uint32_t)((W_OFF + (c & 1) * WBUF) * 2);
        int row = tid >> 1, sg0 = (tid & 1) * 8;
        const __half* src = g_Wt + (size_t)row * 1024 + c * 128 + sg0 * 8;
        uint32_t dst = base + (uint32_t)((row * STH + sg0 * 8) * 2);
#pragma unroll
        for (int sg = 0; sg < 8; sg++) cpa16(dst + sg * 16, src + sg * 8);
    };

    // prologue: B + A (full) + W0 in group0; W1 in group1
#pragma unroll
    for (int it = 0; it < 16; it++) {
        int f = it * 256 + tid;
        int r = f >> 4, c8 = (f & 15) * 8;
        cpa16(sb + (uint32_t)((B_OFF + r * STH + c8) * 2), gB + (size_t)r * 128 + c8);
        cpa16(sb + (uint32_t)((A_OFF + r * STH + c8) * 2), gA + (size_t)r * 128 + c8);
    }
    prefetchW(0);
    cpa_commit();          // g0
    prefetchW(1);
    cpa_commit();          // g1

    float outAcc[4][2][4];
#pragma unroll
    for (int mt = 0; mt < 4; mt++)
#pragma unroll
        for (int nt = 0; nt < 2; nt++)
#pragma unroll
            for (int q = 0; q < 4; q++) outAcc[mt][nt][q] = 0.f;

    // ldmatrix bases
    // phase A (A resident, gather rows (l_loc, ic*4+di)):
    //   cr = mt*16 + (lane&15); full row = mt*128 + ((lane&15)>>2)*32 + ic*4 + (lane&3)
    uint32_t aBaseA = sb + (uint32_t)((A_OFF + (((lane & 15) >> 2) * 32 + (lane & 3)) * STH
                                       + (lane >> 4) * 8) * 2);
    uint32_t bAddrA = sb + (uint32_t)((B_OFF + (w * 32 + ((lane >> 4) & 1) * 8 + (lane & 7)) * STH
                                       + ((lane >> 3) & 1) * 8) * 2);
    uint32_t aAddrB = sb + (uint32_t)((G_OFF + (lane & 15) * STH + (lane >> 4) * 8) * 2);
    uint32_t bAddrW0 = (uint32_t)((W_OFF + (w * 16 + ((lane >> 4) & 1) * 8 + (lane & 7)) * STH
                                   + ((lane >> 3) & 1) * 8) * 2);

    cpa_wait<1>();      // g0 (A, B, W0) complete
    __syncthreads();

#pragma unroll 1
    for (int ic = 0; ic < 8; ic++) {
        if (ic > 0) {
            __syncthreads();                 // Gs consumed; W slot (ic+1)&1 free
            if (ic < 7) { prefetchW(ic + 1); cpa_commit(); }
        }

        // ---- phase A: Gc[32 x 256] = A_sub @ B^T (K=128), pipelined ----
        uint32_t aA = aBaseA + (uint32_t)((ic * 4 * STH) * 2);
        float accA[2][4][4];
#pragma unroll
        for (int mt = 0; mt < 2; mt++)
#pragma unroll
            for (int nt = 0; nt < 4; nt++)
#pragma unroll
                for (int q = 0; q < 4; q++) accA[mt][nt][q] = 0.f;

        {
            uint32_t aF[2][2][4], bF[2][2][4];
#pragma unroll
            for (int mt = 0; mt < 2; mt++)
                ldsm4(aF[0][mt][0], aF[0][mt][1], aF[0][mt][2], aF[0][mt][3],
                      aA + (uint32_t)((mt * 128 * STH) * 2));
#pragma unroll
            for (int pr = 0; pr < 2; pr++)
                ldsm4(bF[0][pr][0], bF[0][pr][1], bF[0][pr][2], bF[0][pr][3],
                      bAddrA + (uint32_t)((pr * 16 * STH) * 2));
#pragma unroll
            for (int ks = 0; ks < 8; ks++) {
                int cur = ks & 1, nxt = cur ^ 1;
                if (ks < 7) {
#pragma unroll
                    for (int mt = 0; mt < 2; mt++)
                        ldsm4(aF[nxt][mt][0], aF[nxt][mt][1], aF[nxt][mt][2], aF[nxt][mt][3],
                              aA + (uint32_t)((mt * 128 * STH + (ks + 1) * 16) * 2));
#pragma unroll
                    for (int pr = 0; pr < 2; pr++)
                        ldsm4(bF[nxt][pr][0], bF[nxt][pr][1], bF[nxt][pr][2], bF[nxt][pr][3],
                              bAddrA + (uint32_t)((pr * 16 * STH + (ks + 1) * 16) * 2));
                }
#pragma unroll
                for (int mt = 0; mt < 2; mt++)
#pragma unroll
                    for (int nt = 0; nt < 4; nt++)
                        mma16816(accA[mt][nt], aF[cur][mt],
                                 bF[cur][nt >> 1][(nt & 1) * 2],
                                 bF[cur][nt >> 1][(nt & 1) * 2 + 1]);
            }
        }

        // ---- store Gc -> Gs[pair][ij_local] fp16 ----
        {
            int rB = lane >> 2, jB = (lane & 3) * 2;
#pragma unroll
            for (int mt = 0; mt < 2; mt++) {
                int r = mt * 16 + rB;
                int q = (r & 3) * 32 + jB;
                int p = (r >> 2) * 8 + w;
#pragma unroll
                for (int nt = 0; nt < 4; nt++) {
                    *(uint32_t*)(smh + G_OFF + p * STH + q + nt * 8) =
                        pack2h(accA[mt][nt][0], accA[mt][nt][1]);
                    *(uint32_t*)(smh + G_OFF + (p + 16) * STH + q + nt * 8) =
                        pack2h(accA[mt][nt][2], accA[mt][nt][3]);
                }
            }
        }
        if (ic < 7) { cpa_wait<1>(); } else { cpa_wait<0>(); }
        __syncthreads();                 // Gs + W[ic] visible

        // ---- phase B: out += Gs[64x128] @ W[128x128]^T, pipelined ----
        uint32_t sW = sb + (uint32_t)((ic & 1) * WBUF * 2) + bAddrW0;
        {
            uint32_t aF[2][4][4], bF[2][4];
#pragma unroll
            for (int mt = 0; mt < 4; mt++)
                ldsm4(aF[0][mt][0], aF[0][mt][1], aF[0][mt][2], aF[0][mt][3],
                      aAddrB + (uint32_t)((mt * 16 * STH) * 2));
            ldsm4(bF[0][0], bF[0][1], bF[0][2], bF[0][3], sW);
#pragma unroll
            for (int ks = 0; ks < 8; ks++) {
                int cur = ks & 1, nxt = cur ^ 1;
                if (ks < 7) {
#pragma unroll
                    for (int mt = 0; mt < 4; mt++)
                        ldsm4(aF[nxt][mt][0], aF[nxt][mt][1], aF[nxt][mt][2], aF[nxt][mt][3],
                              aAddrB + (uint32_t)((mt * 16 * STH + (ks + 1) * 16) * 2));
                    ldsm4(bF[nxt][0], bF[nxt][1], bF[nxt][2], bF[nxt][3],
                          sW + (uint32_t)(((ks + 1) * 16) * 2));
                }
#pragma unroll
                for (int mt = 0; mt < 4; mt++) {
                    mma16816(outAcc[mt][0], aF[cur][mt], bF[cur][0], bF[cur][1]);
                    mma16816(outAcc[mt][1], aF[cur][mt], bF[cur][2], bF[cur][3]);
                }
            }
        }
    }
    __syncthreads();

    // ---- epilogue: stage f32 in B region (stride 132), coalesced writes ----
    {
        int rB = lane >> 2, nB = (lane & 3) * 2;
#pragma unroll
        for (int mt = 0; mt < 4; mt++) {
            int p = mt * 16 + rB;
#pragma unroll
            for (int nt = 0; nt < 2; nt++) {
                int nc = w * 16 + nt * 8 + nB;
                *(float2*)&smf[p * 132 + nc] =
                    make_float2(outAcc[mt][nt][0], outAcc[mt][nt][1]);
                *(float2*)&smf[(p + 8) * 132 + nc] =
                    make_float2(outAcc[mt][nt][2], outAcc[mt][nt][3]);
            }
        }
    }
    __syncthreads();

#pragma unroll
    for (int it = 0; it < 8; it++) {
        int f = it * 256 + tid;
        int p = f >> 5;
        int c4 = (f & 31) * 4;
        int l = bl * 8 + (p >> 3);
        int m = bm * 8 + (p & 7);
        size_t o = ((size_t)(l * L_ + m)) * DP + c4;
        float4 v = *(float4*)&smf[p * 132 + c4];
        float4 pv = *(const float4*)&pairin[o];
        float4 bv = *(const float4*)&bo[c4];
        v.x += pv.x + bv.x; v.y += pv.y + bv.y;
        v.z += pv.z + bv.z; v.w += pv.w + bv.w;
        *(float4*)&outp[o] = v;
    }
}

// ---------------------------------------------------------------------------
// Launch
// ---------------------------------------------------------------------------
extern "C" void kernel_launch(void* const* d_in, const int* in_sizes, int n_in,
                              void* d_out, int out_size)
{
    const float* msa    = (const float*)d_in[0];
    const float* pairin = (const float*)d_in[1];
    const float* gamma  = (const float*)d_in[4];
    const float* beta   = (const float*)d_in[5];
    const float* wl     = (const float*)d_in[6];
    const float* bleft  = (const float*)d_in[7];
    const float* wr     = (const float*)d_in[8];
    const float* bright = (const float*)d_in[9];
    const float* wo     = (const float*)d_in[10];
    const float* bo     = (const float*)d_in[11];
    float* outp = (float*)d_out;

    int smemLn = 192 * XST * 2;
    cudaFuncSetAttribute(ln_proj_kernel,
                         cudaFuncAttributeMaxDynamicSharedMemorySize, smemLn);
    cudaFuncSetAttribute(fused_gemm_kernel,
                         cudaFuncAttributeMaxDynamicSharedMemorySize, SMEM_FUSED);

    ln_proj_kernel<<<256, 256, smemLn>>>(msa, gamma, beta, wl, bleft, wr, bright);
    wt_kernel<<<512, 256>>>(wo);
    fused_gemm_kernel<<<dim3(32, 32), 256, SMEM_FUSED>>>(pairin, bo, outp);
}

// round 9
// speedup vs baseline: 1.2161x; 1.1233x over previous
#include <cuda_runtime.h>
#include <cuda_fp16.h>
#include <cstdint>

// Shapes (fixed)
constexpr int N_  = 128;
constexpr int L_  = 256;
constexpr int DM  = 256;
constexpr int DP  = 128;

// Device scratch (fp16)
__device__ __half g_A[8192 * 128];   // [(l*32+i)][s]
__device__ __half g_B[8192 * 128];   // [(m*32+j)][s]
__device__ __half g_Wt[DP * 1024];   // [n][ij]

// ---------------------------------------------------------------------------
// helpers
// ---------------------------------------------------------------------------
__device__ __forceinline__ uint32_t smem_u32(const void* p) {
    uint32_t a;
    asm("{ .reg .u64 t; cvta.to.shared.u64 t, %1; cvt.u32.u64 %0, t; }"
        : "=r"(a) : "l"(p));
    return a;
}
__device__ __forceinline__ void ldsm4(uint32_t& r0, uint32_t& r1,
                                      uint32_t& r2, uint32_t& r3, uint32_t a) {
    asm volatile("ldmatrix.sync.aligned.m8n8.x4.shared.b16 {%0,%1,%2,%3}, [%4];"
                 : "=r"(r0), "=r"(r1), "=r"(r2), "=r"(r3) : "r"(a));
}
__device__ __forceinline__ void mma16816(float* d, const uint32_t* a,
                                         uint32_t b0, uint32_t b1) {
    asm volatile(
        "mma.sync.aligned.m16n8k16.row.col.f32.f16.f16.f32 "
        "{%0,%1,%2,%3}, {%4,%5,%6,%7}, {%8,%9}, {%0,%1,%2,%3};"
        : "+f"(d[0]), "+f"(d[1]), "+f"(d[2]), "+f"(d[3])
        : "r"(a[0]), "r"(a[1]), "r"(a[2]), "r"(a[3]), "r"(b0), "r"(b1));
}
__device__ __forceinline__ void cpa16(uint32_t dst, const void* src) {
    asm volatile("cp.async.cg.shared.global [%0], [%1], 16;"
                 :: "r"(dst), "l"(src) : "memory");
}
__device__ __forceinline__ void cpa_commit() {
    asm volatile("cp.async.commit_group;" ::: "memory");
}
template <int N>
__device__ __forceinline__ void cpa_wait() {
    asm volatile("cp.async.wait_group %0;" :: "n"(N) : "memory");
}
__device__ __forceinline__ uint32_t pack2h(float a, float b) {
    __half2 h = __floats2half2_rn(a, b);
    return *(uint32_t*)&h;
}

// ---------------------------------------------------------------------------
// Kernel 1: LN + projections via tensor cores (round-6 version, proven).
// ---------------------------------------------------------------------------
constexpr int XST = 264;

__global__ void __launch_bounds__(256) ln_proj_kernel(
    const float* __restrict__ msa,
    const float* __restrict__ gamma,
    const float* __restrict__ beta,
    const float* __restrict__ wl,
    const float* __restrict__ bleft,
    const float* __restrict__ wr,
    const float* __restrict__ bright)
{
    extern __shared__ __half sh[];
    __half* Xs = sh;                    // [128][264]
    __half* Wt = sh + 128 * XST;        // [64][264]
    float*  Osm = (float*)sh;           // reuse X region: [64][132]

    int tid = threadIdx.x, lane = tid & 31, w = tid >> 5;
    int l = blockIdx.x;

    for (int e = tid; e < 8192; e += 256) {
        int d = e >> 5, h = e & 31;
        Wt[h * XST + d]        = __float2half_rn(wl[e]);
        Wt[(h + 32) * XST + d] = __float2half_rn(wr[e]);
    }

    float4 ga0 = *(const float4*)&gamma[lane * 8];
    float4 ga1 = *(const float4*)&gamma[lane * 8 + 4];
    float4 be0 = *(const float4*)&beta[lane * 8];
    float4 be1 = *(const float4*)&beta[lane * 8 + 4];

#pragma unroll 2
    for (int rr = 0; rr < 16; rr++) {
        int s = w * 16 + rr;
        const float* x = msa + ((size_t)s * L_ + l) * DM;
        float4 x0 = *(const float4*)&x[lane * 8];
        float4 x1 = *(const float4*)&x[lane * 8 + 4];
        float sum = x0.x + x0.y + x0.z + x0.w + x1.x + x1.y + x1.z + x1.w;
        float sq  = x0.x*x0.x + x0.y*x0.y + x0.z*x0.z + x0.w*x0.w
                  + x1.x*x1.x + x1.y*x1.y + x1.z*x1.z + x1.w*x1.w;
#pragma unroll
        for (int o = 16; o > 0; o >>= 1) {
            sum += __shfl_xor_sync(0xffffffffu, sum, o);
            sq  += __shfl_xor_sync(0xffffffffu, sq,  o);
        }
        float mu = sum * (1.f / DM);
        float rstd = rsqrtf(sq * (1.f / DM) - mu * mu + 1e-5f);
        uint4 pk;
        pk.x = pack2h((x0.x - mu) * rstd * ga0.x + be0.x,
                      (x0.y - mu) * rstd * ga0.y + be0.y);
        pk.y = pack2h((x0.z - mu) * rstd * ga0.z + be0.z,
                      (x0.w - mu) * rstd * ga0.w + be0.w);
        pk.z = pack2h((x1.x - mu) * rstd * ga1.x + be1.x,
                      (x1.y - mu) * rstd * ga1.y + be1.y);
        pk.w = pack2h((x1.z - mu) * rstd * ga1.z + be1.z,
                      (x1.w - mu) * rstd * ga1.w + be1.w);
        *(uint4*)&Xs[s * XST + lane * 8] = pk;
    }
    __syncthreads();

    int wm = w >> 1, wn = w & 1;
    float acc[2][4][4];
#pragma unroll
    for (int mt = 0; mt < 2; mt++)
#pragma unroll
        for (int nt = 0; nt < 4; nt++)
#pragma unroll
            for (int q = 0; q < 4; q++) acc[mt][nt][q] = 0.f;

    uint32_t sb = smem_u32(sh);
    uint32_t aAddr = sb + (uint32_t)(((wm * 32 + (lane & 15)) * XST + (lane >> 4) * 8) * 2);
    uint32_t bAddr = sb + (uint32_t)((128 * XST
                    + (wn * 32 + ((lane >> 4) & 1) * 8 + (lane & 7)) * XST
                    + ((lane >> 3) & 1) * 8) * 2);

#pragma unroll
    for (int ks = 0; ks < 16; ks++) {
        uint32_t a[2][4], b[2][4];
#pragma unroll
        for (int mt = 0; mt < 2; mt++)
            ldsm4(a[mt][0], a[mt][1], a[mt][2], a[mt][3],
                  aAddr + (uint32_t)((mt * 16 * XST + ks * 16) * 2));
#pragma unroll
        for (int n2 = 0; n2 < 2; n2++)
            ldsm4(b[n2][0], b[n2][1], b[n2][2], b[n2][3],
                  bAddr + (uint32_t)((n2 * 16 * XST + ks * 16) * 2));
#pragma unroll
        for (int mt = 0; mt < 2; mt++)
#pragma unroll
            for (int nt = 0; nt < 4; nt++)
                mma16816(acc[mt][nt], a[mt],
                         b[nt >> 1][(nt & 1) * 2], b[nt >> 1][(nt & 1) * 2 + 1]);
    }
    __syncthreads();

    {
        int rB = lane >> 2, cB = (lane & 3) * 2;
#pragma unroll
        for (int mt = 0; mt < 2; mt++) {
            int r = wm * 32 + mt * 16 + rB;
#pragma unroll
            for (int nt = 0; nt < 4; nt++) {
                int c = wn * 32 + nt * 8 + cB;
                Osm[c * 132 + r]            = acc[mt][nt][0];
                Osm[(c + 1) * 132 + r]      = acc[mt][nt][1];
                Osm[c * 132 + r + 8]        = acc[mt][nt][2];
                Osm[(c + 1) * 132 + r + 8]  = acc[mt][nt][3];
            }
        }
    }
    __syncthreads();

    {
        int n = tid >> 2, s0 = (tid & 3) * 32;
        bool isL = n < 32;
        int hh = isL ? n : n - 32;
        float bias = isL ? bleft[hh] : bright[hh];
        float scale = isL ? 1.f : (1.f / 128.f);
        __half* dst = (isL ? g_A : g_B) + (size_t)(l * 32 + hh) * 128 + s0;
#pragma unroll
        for (int q = 0; q < 4; q++) {
            float4 v0 = *(float4*)&Osm[n * 132 + s0 + q * 8];
            float4 v1 = *(float4*)&Osm[n * 132 + s0 + q * 8 + 4];
            uint4 pk;
            pk.x = pack2h((v0.x + bias) * scale, (v0.y + bias) * scale);
            pk.y = pack2h((v0.z + bias) * scale, (v0.w + bias) * scale);
            pk.z = pack2h((v1.x + bias) * scale, (v1.y + bias) * scale);
            pk.w = pack2h((v1.z + bias) * scale, (v1.w + bias) * scale);
            *(uint4*)(dst + q * 8) = pk;
        }
    }
}

// ---------------------------------------------------------------------------
// w_out transpose to fp16: g_Wt[n][ij]
// ---------------------------------------------------------------------------
__global__ void __launch_bounds__(256) wt_kernel(const float* __restrict__ wo)
{
    int idx = blockIdx.x * 256 + threadIdx.x;
    int k = idx >> 7, n = idx & 127;
    g_Wt[(size_t)n * 1024 + k] = __float2half_rn(wo[idx]);
}

// ---------------------------------------------------------------------------
// Fused GEMM, fp16 MMA. CTA = 16 l x 8 m = 128 pairs, grid (16,32).
//   4x4 warp tiles in BOTH phases (LDS <= 96 B/cyc/SM, under the 128 cap).
//   Phase A: D[256 m-rows x 64 A-rows], warp grid 4x2.
//   Phase B: D[128 pairs x 128 n],      warp grid 2x4.
// ---------------------------------------------------------------------------
constexpr int STH   = 136;                      // halves
constexpr int B_OFF = 0;                        // [256][136]  (8m x 32j rows)
constexpr int A_OFF = 256 * STH;                // 2 x [64][136] (16l x 4di)
constexpr int ABUF  = 64 * STH;
constexpr int G_OFF = A_OFF + 2 * ABUF;         // [128][136] pairs x ij
constexpr int W_OFF = G_OFF + 128 * STH;        // 2 x [128][136]
constexpr int WBUF  = 128 * STH;
constexpr int SMEM_FUSED = (W_OFF + 2 * WBUF) * 2;   // 208896 bytes

__global__ void __launch_bounds__(256, 1) fused_gemm_kernel(
    const float* __restrict__ pairin,
    const float* __restrict__ bo,
    float* __restrict__ outp)
{
    extern __shared__ __half smh[];
    float* smf = (float*)smh;
    uint32_t sb = smem_u32(smh);
    int tid = threadIdx.x, lane = tid & 31, w = tid >> 5;
    int bl = blockIdx.x, bm = blockIdx.y;

    const __half* gA = g_A + (size_t)(bl * 512) * 128;   // 16 l * 32 i rows
    const __half* gB = g_B + (size_t)(bm * 256) * 128;   // 8 m * 32 j rows

    auto prefetchW = [&](int c) {   // W chunk c -> slot c&1 (2048 cpa16)
        uint32_t base = sb + (uint32_t)((W_OFF + (c & 1) * WBUF) * 2);
        int row = tid >> 1, sg0 = (tid & 1) * 8;
        const __half* src = g_Wt + (size_t)row * 1024 + c * 128 + sg0 * 8;
        uint32_t dst = base + (uint32_t)((row * STH + sg0 * 8) * 2);
#pragma unroll
        for (int sg = 0; sg < 8; sg++) cpa16(dst + sg * 16, src + sg * 8);
    };
    auto prefetchA = [&](int c) {   // A chunk c (64 rows) -> slot c&1 (1024 cpa16)
        uint32_t base = sb + (uint32_t)((A_OFF + (c & 1) * ABUF) * 2);
#pragma unroll
        for (int it = 0; it < 4; it++) {
            int f = it * 256 + tid;
            int r = f >> 4, c8 = (f & 15) * 8;           // r: lloc*4+di
            int grow = (r >> 2) * 32 + c * 4 + (r & 3);
            cpa16(base + (uint32_t)((r * STH + c8) * 2),
                  gA + (size_t)grow * 128 + c8);
        }
    };

    // prologue group0: B + A[0] + W[0]
#pragma unroll
    for (int it = 0; it < 16; it++) {
        int f = it * 256 + tid;
        int r = f >> 4, c8 = (f & 15) * 8;
        cpa16(sb + (uint32_t)((B_OFF + r * STH + c8) * 2),
              gB + (size_t)r * 128 + c8);
    }
    prefetchA(0);
    prefetchW(0);
    cpa_commit();

    float outAcc[4][4][4];
#pragma unroll
    for (int mt = 0; mt < 4; mt++)
#pragma unroll
        for (int nt = 0; nt < 4; nt++)
#pragma unroll
            for (int q = 0; q < 4; q++) outAcc[mt][nt][q] = 0.f;

    // ---- ldmatrix bases ----
    int wmA = w >> 1, wnA = w & 1;     // phase A: 4 m-groups x 2 n-groups
    int wmB = w >> 2, wnB = w & 3;     // phase B: 2 pair-groups x 4 n-groups

    uint32_t aAddrA = sb + (uint32_t)((B_OFF + (wmA * 64 + (lane & 15)) * STH
                                       + (lane >> 4) * 8) * 2);
    uint32_t bAddrA0 = sb + (uint32_t)((A_OFF + (wnA * 32 + ((lane >> 4) & 1) * 8 + (lane & 7)) * STH
                                        + ((lane >> 3) & 1) * 8) * 2);
    uint32_t aAddrB = sb + (uint32_t)((G_OFF + (wmB * 64 + (lane & 15)) * STH
                                       + (lane >> 4) * 8) * 2);
    uint32_t bAddrW0 = (uint32_t)((W_OFF + (wnB * 32 + ((lane >> 4) & 1) * 8 + (lane & 7)) * STH
                                   + ((lane >> 3) & 1) * 8) * 2);

    cpa_wait<0>();
    __syncthreads();

#pragma unroll 1
    for (int ic = 0; ic < 8; ic++) {
        if (ic > 0) __syncthreads();     // phase B(ic-1) done: Gs, W/A slots free
        if (ic < 7) {
            prefetchA(ic + 1);
            prefetchW(ic + 1);
            cpa_commit();
            cpa_wait<1>();               // group(ic) done (no-op for ic=0)
        } else {
            cpa_wait<0>();
        }
        if (ic > 0) __syncthreads();     // A[ic] (loaded last iter... visible) + W[ic]

        // ---- phase A: D[256 m-rows x 64 A-rows], K=128 s, 4x4 tiles ----
        uint32_t bA = bAddrA0 + (uint32_t)((ic & 1) * ABUF * 2);
        float accA[4][4][4];
#pragma unroll
        for (int mt = 0; mt < 4; mt++)
#pragma unroll
            for (int nt = 0; nt < 4; nt++)
#pragma unroll
                for (int q = 0; q < 4; q++) accA[mt][nt][q] = 0.f;

#pragma unroll
        for (int ks = 0; ks < 8; ks++) {
            uint32_t a[4][4], b[2][4];
#pragma unroll
            for (int mt = 0; mt < 4; mt++)
                ldsm4(a[mt][0], a[mt][1], a[mt][2], a[mt][3],
                      aAddrA + (uint32_t)((mt * 16 * STH + ks * 16) * 2));
#pragma unroll
            for (int pr = 0; pr < 2; pr++)
                ldsm4(b[pr][0], b[pr][1], b[pr][2], b[pr][3],
                      bA + (uint32_t)((pr * 16 * STH + ks * 16) * 2));
#pragma unroll
            for (int mt = 0; mt < 4; mt++)
#pragma unroll
                for (int nt = 0; nt < 4; nt++)
                    mma16816(accA[mt][nt], a[mt],
                             b[nt >> 1][(nt & 1) * 2], b[nt >> 1][(nt & 1) * 2 + 1]);
        }

        // ---- scatter accA -> Gs[pair][ij_local] (fp16 scalar stores) ----
        {
            int rB = lane >> 2, cB = (lane & 3) * 2;
#pragma unroll
            for (int mt = 0; mt < 4; mt++) {
                int rbase = wmA * 64 + mt * 16 + rB;      // m-row: mloc*32+j
#pragma unroll
                for (int nt = 0; nt < 4; nt++) {
                    int cbase = wnA * 32 + nt * 8 + cB;   // A-row: lloc*4+di
#pragma unroll
                    for (int q = 0; q < 4; q++) {
                        int r = rbase + ((q >> 1) & 1) * 8;
                        int c = cbase + (q & 1);
                        int p = ((c >> 2) << 3) + (r >> 5);     // lloc*8+mloc
                        int col = (c & 3) * 32 + (r & 31);      // di*32+j
                        smh[G_OFF + p * STH + col] = __float2half_rn(accA[mt][nt][q]);
                    }
                }
            }
        }
        __syncthreads();                 // Gs visible

        // ---- phase B: D[128 pairs x 128 n] += Gs @ W[ic]^T, 4x4 tiles ----
        uint32_t sW = sb + bAddrW0 + (uint32_t)((ic & 1) * WBUF * 2);
#pragma unroll
        for (int ks = 0; ks < 8; ks++) {
            uint32_t a[4][4], b[2][4];
#pragma unroll
            for (int mt = 0; mt < 4; mt++)
                ldsm4(a[mt][0], a[mt][1], a[mt][2], a[mt][3],
                      aAddrB + (uint32_t)((mt * 16 * STH + ks * 16) * 2));
#pragma unroll
            for (int pr = 0; pr < 2; pr++)
                ldsm4(b[pr][0], b[pr][1], b[pr][2], b[pr][3],
                      sW + (uint32_t)((pr * 16 * STH + ks * 16) * 2));
#pragma unroll
            for (int mt = 0; mt < 4; mt++)
#pragma unroll
                for (int nt = 0; nt < 4; nt++)
                    mma16816(outAcc[mt][nt], a[mt],
                             b[nt >> 1][(nt & 1) * 2], b[nt >> 1][(nt & 1) * 2 + 1]);
        }
    }
    __syncthreads();

    // ---- epilogue: stage f32 in B region (stride 132), coalesced writes ----
    {
        int rB = lane >> 2, nB = (lane & 3) * 2;
#pragma unroll
        for (int mt = 0; mt < 4; mt++) {
            int p = wmB * 64 + mt * 16 + rB;
#pragma unroll
            for (int nt = 0; nt < 4; nt++) {
                int nc = wnB * 32 + nt * 8 + nB;
                *(float2*)&smf[p * 132 + nc] =
                    make_float2(outAcc[mt][nt][0], outAcc[mt][nt][1]);
                *(float2*)&smf[(p + 8) * 132 + nc] =
                    make_float2(outAcc[mt][nt][2], outAcc[mt][nt][3]);
            }
        }
    }
    __syncthreads();

#pragma unroll
    for (int it = 0; it < 16; it++) {
        int f = it * 256 + tid;          // 4096 float4
        int p = f >> 5;                  // pair 0..127 (= lloc*8+mloc)
        int c4 = (f & 31) * 4;
        int l = bl * 16 + (p >> 3);
        int m = bm * 8 + (p & 7);
        size_t o = ((size_t)(l * L_ + m)) * DP + c4;
        float4 v = *(float4*)&smf[p * 132 + c4];
        float4 pv = *(const float4*)&pairin[o];
        float4 bv = *(const float4*)&bo[c4];
        v.x += pv.x + bv.x; v.y += pv.y + bv.y;
        v.z += pv.z + bv.z; v.w += pv.w + bv.w;
        *(float4*)&outp[o] = v;
    }
}

// ---------------------------------------------------------------------------
// Launch
// ---------------------------------------------------------------------------
extern "C" void kernel_launch(void* const* d_in, const int* in_sizes, int n_in,
                              void* d_out, int out_size)
{
    const float* msa    = (const float*)d_in[0];
    const float* pairin = (const float*)d_in[1];
    const float* gamma  = (const float*)d_in[4];
    const float* beta   = (const float*)d_in[5];
    const float* wl     = (const float*)d_in[6];
    const float* bleft  = (const float*)d_in[7];
    const float* wr     = (const float*)d_in[8];
    const float* bright = (const float*)d_in[9];
    const float* wo     = (const float*)d_in[10];
    const float* bo     = (const float*)d_in[11];
    float* outp = (float*)d_out;

    int smemLn = 192 * XST * 2;
    cudaFuncSetAttribute(ln_proj_kernel,
                         cudaFuncAttributeMaxDynamicSharedMemorySize, smemLn);
    cudaFuncSetAttribute(fused_gemm_kernel,
                         cudaFuncAttributeMaxDynamicSharedMemorySize, SMEM_FUSED);

    ln_proj_kernel<<<256, 256, smemLn>>>(msa, gamma, beta, wl, bleft, wr, bright);
    wt_kernel<<<512, 256>>>(wo);
    fused_gemm_kernel<<<dim3(16, 32), 256, SMEM_FUSED>>>(pairin, bo, outp);
}

// round 10
// speedup vs baseline: 1.3506x; 1.1106x over previous
#include <cuda_runtime.h>
#include <cuda_fp16.h>
#include <cstdint>

// Shapes (fixed)
constexpr int N_  = 128;
constexpr int L_  = 256;
constexpr int DM  = 256;
constexpr int DP  = 128;

// Device scratch (fp16)
__device__ __half g_A[8192 * 128];   // [(l*32+i)][s]
__device__ __half g_B[8192 * 128];   // [(m*32+j)][s]
__device__ __half g_Wt[DP * 1024];   // [n][ij]

// ---------------------------------------------------------------------------
// helpers
// ---------------------------------------------------------------------------
__device__ __forceinline__ uint32_t smem_u32(const void* p) {
    uint32_t a;
    asm("{ .reg .u64 t; cvta.to.shared.u64 t, %1; cvt.u32.u64 %0, t; }"
        : "=r"(a) : "l"(p));
    return a;
}
__device__ __forceinline__ void ldsm4(uint32_t& r0, uint32_t& r1,
                                      uint32_t& r2, uint32_t& r3, uint32_t a) {
    asm volatile("ldmatrix.sync.aligned.m8n8.x4.shared.b16 {%0,%1,%2,%3}, [%4];"
                 : "=r"(r0), "=r"(r1), "=r"(r2), "=r"(r3) : "r"(a));
}
__device__ __forceinline__ void mma16816(float* d, const uint32_t* a,
                                         uint32_t b0, uint32_t b1) {
    asm volatile(
        "mma.sync.aligned.m16n8k16.row.col.f32.f16.f16.f32 "
        "{%0,%1,%2,%3}, {%4,%5,%6,%7}, {%8,%9}, {%0,%1,%2,%3};"
        : "+f"(d[0]), "+f"(d[1]), "+f"(d[2]), "+f"(d[3])
        : "r"(a[0]), "r"(a[1]), "r"(a[2]), "r"(a[3]), "r"(b0), "r"(b1));
}
__device__ __forceinline__ void cpa16(uint32_t dst, const void* src) {
    asm volatile("cp.async.cg.shared.global [%0], [%1], 16;"
                 :: "r"(dst), "l"(src) : "memory");
}
__device__ __forceinline__ void cpa_commit() {
    asm volatile("cp.async.commit_group;" ::: "memory");
}
template <int N>
__device__ __forceinline__ void cpa_wait() {
    asm volatile("cp.async.wait_group %0;" :: "n"(N) : "memory");
}
__device__ __forceinline__ uint32_t pack2h(float a, float b) {
    __half2 h = __floats2half2_rn(a, b);
    return *(uint32_t*)&h;
}

// ---------------------------------------------------------------------------
// Kernel 1: LN + projections via tensor cores. Batched LN loads (MLP 8).
// ---------------------------------------------------------------------------
constexpr int XST = 264;

__global__ void __launch_bounds__(256) ln_proj_kernel(
    const float* __restrict__ msa,
    const float* __restrict__ gamma,
    const float* __restrict__ beta,
    const float* __restrict__ wl,
    const float* __restrict__ bleft,
    const float* __restrict__ wr,
    const float* __restrict__ bright)
{
    extern __shared__ __half sh[];
    __half* Xs = sh;                    // [128][264]
    __half* Wt = sh + 128 * XST;        // [64][264]
    float*  Osm = (float*)sh;           // reuse X region: [64][132]

    int tid = threadIdx.x, lane = tid & 31, w = tid >> 5;
    int l = blockIdx.x;

    for (int e = tid; e < 8192; e += 256) {
        int d = e >> 5, h = e & 31;
        Wt[h * XST + d]        = __float2half_rn(wl[e]);
        Wt[(h + 32) * XST + d] = __float2half_rn(wr[e]);
    }

    float4 ga0 = *(const float4*)&gamma[lane * 8];
    float4 ga1 = *(const float4*)&gamma[lane * 8 + 4];
    float4 be0 = *(const float4*)&beta[lane * 8];
    float4 be1 = *(const float4*)&beta[lane * 8 + 4];

#pragma unroll 1
    for (int rr4 = 0; rr4 < 4; rr4++) {
        float4 x0[4], x1[4];
#pragma unroll
        for (int r = 0; r < 4; r++) {
            int s = w * 16 + rr4 * 4 + r;
            const float* x = msa + ((size_t)s * L_ + l) * DM;
            x0[r] = *(const float4*)&x[lane * 8];
            x1[r] = *(const float4*)&x[lane * 8 + 4];
        }
#pragma unroll
        for (int r = 0; r < 4; r++) {
            int s = w * 16 + rr4 * 4 + r;
            float sum = x0[r].x + x0[r].y + x0[r].z + x0[r].w
                      + x1[r].x + x1[r].y + x1[r].z + x1[r].w;
            float sq  = x0[r].x*x0[r].x + x0[r].y*x0[r].y + x0[r].z*x0[r].z + x0[r].w*x0[r].w
                      + x1[r].x*x1[r].x + x1[r].y*x1[r].y + x1[r].z*x1[r].z + x1[r].w*x1[r].w;
#pragma unroll
            for (int o = 16; o > 0; o >>= 1) {
                sum += __shfl_xor_sync(0xffffffffu, sum, o);
                sq  += __shfl_xor_sync(0xffffffffu, sq,  o);
            }
            float mu = sum * (1.f / DM);
            float rstd = rsqrtf(sq * (1.f / DM) - mu * mu + 1e-5f);
            uint4 pk;
            pk.x = pack2h((x0[r].x - mu) * rstd * ga0.x + be0.x,
                          (x0[r].y - mu) * rstd * ga0.y + be0.y);
            pk.y = pack2h((x0[r].z - mu) * rstd * ga0.z + be0.z,
                          (x0[r].w - mu) * rstd * ga0.w + be0.w);
            pk.z = pack2h((x1[r].x - mu) * rstd * ga1.x + be1.x,
                          (x1[r].y - mu) * rstd * ga1.y + be1.y);
            pk.w = pack2h((x1[r].z - mu) * rstd * ga1.z + be1.z,
                          (x1[r].w - mu) * rstd * ga1.w + be1.w);
            *(uint4*)&Xs[s * XST + lane * 8] = pk;
        }
    }
    __syncthreads();

    int wm = w >> 1, wn = w & 1;
    float acc[2][4][4];
#pragma unroll
    for (int mt = 0; mt < 2; mt++)
#pragma unroll
        for (int nt = 0; nt < 4; nt++)
#pragma unroll
            for (int q = 0; q < 4; q++) acc[mt][nt][q] = 0.f;

    uint32_t sb = smem_u32(sh);
    uint32_t aAddr = sb + (uint32_t)(((wm * 32 + (lane & 15)) * XST + (lane >> 4) * 8) * 2);
    uint32_t bAddr = sb + (uint32_t)((128 * XST
                    + (wn * 32 + ((lane >> 4) & 1) * 8 + (lane & 7)) * XST
                    + ((lane >> 3) & 1) * 8) * 2);

#pragma unroll
    for (int ks = 0; ks < 16; ks++) {
        uint32_t a[2][4], b[2][4];
#pragma unroll
        for (int mt = 0; mt < 2; mt++)
            ldsm4(a[mt][0], a[mt][1], a[mt][2], a[mt][3],
                  aAddr + (uint32_t)((mt * 16 * XST + ks * 16) * 2));
#pragma unroll
        for (int n2 = 0; n2 < 2; n2++)
            ldsm4(b[n2][0], b[n2][1], b[n2][2], b[n2][3],
                  bAddr + (uint32_t)((n2 * 16 * XST + ks * 16) * 2));
#pragma unroll
        for (int mt = 0; mt < 2; mt++)
#pragma unroll
            for (int nt = 0; nt < 4; nt++)
                mma16816(acc[mt][nt], a[mt],
                         b[nt >> 1][(nt & 1) * 2], b[nt >> 1][(nt & 1) * 2 + 1]);
    }
    __syncthreads();

    {
        int rB = lane >> 2, cB = (lane & 3) * 2;
#pragma unroll
        for (int mt = 0; mt < 2; mt++) {
            int r = wm * 32 + mt * 16 + rB;
#pragma unroll
            for (int nt = 0; nt < 4; nt++) {
                int c = wn * 32 + nt * 8 + cB;
                Osm[c * 132 + r]            = acc[mt][nt][0];
                Osm[(c + 1) * 132 + r]      = acc[mt][nt][1];
                Osm[c * 132 + r + 8]        = acc[mt][nt][2];
                Osm[(c + 1) * 132 + r + 8]  = acc[mt][nt][3];
            }
        }
    }
    __syncthreads();

    {
        int n = tid >> 2, s0 = (tid & 3) * 32;
        bool isL = n < 32;
        int hh = isL ? n : n - 32;
        float bias = isL ? bleft[hh] : bright[hh];
        float scale = isL ? 1.f : (1.f / 128.f);
        __half* dst = (isL ? g_A : g_B) + (size_t)(l * 32 + hh) * 128 + s0;
#pragma unroll
        for (int q = 0; q < 4; q++) {
            float4 v0 = *(float4*)&Osm[n * 132 + s0 + q * 8];
            float4 v1 = *(float4*)&Osm[n * 132 + s0 + q * 8 + 4];
            uint4 pk;
            pk.x = pack2h((v0.x + bias) * scale, (v0.y + bias) * scale);
            pk.y = pack2h((v0.z + bias) * scale, (v0.w + bias) * scale);
            pk.z = pack2h((v1.x + bias) * scale, (v1.y + bias) * scale);
            pk.w = pack2h((v1.z + bias) * scale, (v1.w + bias) * scale);
            *(uint4*)(dst + q * 8) = pk;
        }
    }
}

// ---------------------------------------------------------------------------
// w_out transpose to fp16: g_Wt[n][ij]
// ---------------------------------------------------------------------------
__global__ void __launch_bounds__(256) wt_kernel(const float* __restrict__ wo)
{
    int idx = blockIdx.x * 256 + threadIdx.x;
    int k = idx >> 7, n = idx & 127;
    g_Wt[(size_t)n * 1024 + k] = __float2half_rn(wo[idx]);
}

// ---------------------------------------------------------------------------
// Fused GEMM, fp16 MMA. CTA = 16 l x 8 m = 128 pairs, grid (16,32).
//   Phase A: D[64 A-rows x 256 m-rows], warp grid 2x4 (tile 32x64) ->
//            vectorized half2 scatter into Gs.
//   Phase B: D[128 pairs x 128 n], warp grid 2x4, 4x4 fragments.
//   A triple-buffered, W double-buffered, ONE commit group per ic, 2 syncs/ic.
// ---------------------------------------------------------------------------
constexpr int STH   = 136;                      // halves
constexpr int B_OFF = 0;                        // [256][136]  (8m x 32j rows)
constexpr int A_OFF = 256 * STH;                // 3 x [64][136] (16l x 4di)
constexpr int ABUF  = 64 * STH;
constexpr int G_OFF = A_OFF + 3 * ABUF;         // [128][136] pairs x ij
constexpr int W_OFF = G_OFF + 128 * STH;        // 2 x [128][136]
constexpr int WBUF  = 128 * STH;
constexpr int SMEM_FUSED = (W_OFF + 2 * WBUF) * 2;   // 226304 bytes

__global__ void __launch_bounds__(256, 1) fused_gemm_kernel(
    const float* __restrict__ pairin,
    const float* __restrict__ bo,
    float* __restrict__ outp)
{
    extern __shared__ __half smh[];
    float* smf = (float*)smh;
    uint32_t sb = smem_u32(smh);
    int tid = threadIdx.x, lane = tid & 31, w = tid >> 5;
    int bl = blockIdx.x, bm = blockIdx.y;

    const __half* gA = g_A + (size_t)(bl * 512) * 128;   // 16 l * 32 i rows
    const __half* gB = g_B + (size_t)(bm * 256) * 128;   // 8 m * 32 j rows

    auto prefetchW = [&](int c) {   // W chunk c -> slot c&1
        uint32_t base = sb + (uint32_t)((W_OFF + (c & 1) * WBUF) * 2);
        int row = tid >> 1, sg0 = (tid & 1) * 8;
        const __half* src = g_Wt + (size_t)row * 1024 + c * 128 + sg0 * 8;
        uint32_t dst = base + (uint32_t)((row * STH + sg0 * 8) * 2);
#pragma unroll
        for (int sg = 0; sg < 8; sg++) cpa16(dst + sg * 16, src + sg * 8);
    };
    auto prefetchA = [&](int c) {   // A chunk c (64 rows) -> slot c%3
        uint32_t base = sb + (uint32_t)((A_OFF + (c % 3) * ABUF) * 2);
#pragma unroll
        for (int it = 0; it < 4; it++) {
            int f = it * 256 + tid;
            int r = f >> 4, c8 = (f & 15) * 8;           // r: lloc*4+di
            int grow = (r >> 2) * 32 + c * 4 + (r & 3);
            cpa16(base + (uint32_t)((r * STH + c8) * 2),
                  gA + (size_t)grow * 128 + c8);
        }
    };

    // prologue group: B + A0 + A1 + W0
#pragma unroll
    for (int it = 0; it < 16; it++) {
        int f = it * 256 + tid;
        int r = f >> 4, c8 = (f & 15) * 8;
        cpa16(sb + (uint32_t)((B_OFF + r * STH + c8) * 2),
              gB + (size_t)r * 128 + c8);
    }
    prefetchA(0);
    prefetchA(1);
    prefetchW(0);
    cpa_commit();

    float outAcc[4][4][4];
#pragma unroll
    for (int mt = 0; mt < 4; mt++)
#pragma unroll
        for (int nt = 0; nt < 4; nt++)
#pragma unroll
            for (int q = 0; q < 4; q++) outAcc[mt][nt][q] = 0.f;

    // ---- ldmatrix bases ----
    int wm2 = w >> 2;                  // phase A: 2 M-groups (A rows)
    int wn4 = w & 3;                   // phase A: 4 N-groups (m rows)
    int wmB = w >> 2, wnB = w & 3;     // phase B: 2 pair-groups x 4 n-groups

    // phase A: A chunk = M operand (rows 0..63), B tile = N operand
    uint32_t aAddrA0 = sb + (uint32_t)((A_OFF + (wm2 * 32 + (lane & 15)) * STH
                                        + (lane >> 4) * 8) * 2);
    uint32_t bAddrA  = sb + (uint32_t)((B_OFF + (wn4 * 64 + ((lane >> 4) & 1) * 8 + (lane & 7)) * STH
                                        + ((lane >> 3) & 1) * 8) * 2);
    uint32_t aAddrB  = sb + (uint32_t)((G_OFF + (wmB * 64 + (lane & 15)) * STH
                                        + (lane >> 4) * 8) * 2);
    uint32_t bAddrW0 = (uint32_t)((W_OFF + (wnB * 32 + ((lane >> 4) & 1) * 8 + (lane & 7)) * STH
                                   + ((lane >> 3) & 1) * 8) * 2);

    cpa_wait<0>();
    __syncthreads();       // B, A0, A1, W0 visible

#pragma unroll 1
    for (int ic = 0; ic < 8; ic++) {
        if (ic > 0) __syncthreads();     // #1: Gs consumed; A/W slots free
        if (ic < 6) prefetchA(ic + 2);
        if (ic < 7) { prefetchW(ic + 1); cpa_commit(); }

        // ---- phase A: D[64 A-rows x 256 m-rows], K=128 s ----
        uint32_t aA = aAddrA0 + (uint32_t)((ic % 3) * ABUF * 2);
        float accA[2][8][4];
#pragma unroll
        for (int mt = 0; mt < 2; mt++)
#pragma unroll
            for (int nt = 0; nt < 8; nt++)
#pragma unroll
                for (int q = 0; q < 4; q++) accA[mt][nt][q] = 0.f;

#pragma unroll
        for (int ks = 0; ks < 8; ks++) {
            uint32_t a[2][4], b[4][4];
#pragma unroll
            for (int mt = 0; mt < 2; mt++)
                ldsm4(a[mt][0], a[mt][1], a[mt][2], a[mt][3],
                      aA + (uint32_t)((mt * 16 * STH + ks * 16) * 2));
#pragma unroll
            for (int pr = 0; pr < 4; pr++)
                ldsm4(b[pr][0], b[pr][1], b[pr][2], b[pr][3],
                      bAddrA + (uint32_t)((pr * 16 * STH + ks * 16) * 2));
#pragma unroll
            for (int mt = 0; mt < 2; mt++)
#pragma unroll
                for (int nt = 0; nt < 8; nt++)
                    mma16816(accA[mt][nt], a[mt],
                             b[nt >> 1][(nt & 1) * 2], b[nt >> 1][(nt & 1) * 2 + 1]);
        }

        // ---- scatter accA -> Gs[pair][ij_local] (half2 stores) ----
        {
            int rq = lane >> 2, cq = (lane & 3) * 2;
#pragma unroll
            for (int mt = 0; mt < 2; mt++) {
#pragma unroll
                for (int nt = 0; nt < 8; nt++) {
                    int cc = wn4 * 64 + nt * 8 + cq;      // m-row: mloc*32+j
                    int mloc = cc >> 5, jj = cc & 31;
#pragma unroll
                    for (int rh = 0; rh < 2; rh++) {
                        int r = wm2 * 32 + mt * 16 + rh * 8 + rq;  // lloc*4+di
                        int p = (r >> 2) * 8 + mloc;
                        int col = (r & 3) * 32 + jj;
                        *(uint32_t*)(smh + G_OFF + p * STH + col) =
                            pack2h(accA[mt][nt][rh * 2], accA[mt][nt][rh * 2 + 1]);
                    }
                }
            }
        }
        if (ic < 7) { cpa_wait<1>(); } else { cpa_wait<0>(); }
        __syncthreads();                 // #2: Gs + W[ic] + A[ic+1] visible

        // ---- phase B: D[128 pairs x 128 n] += Gs @ W[ic]^T, 4x4 tiles ----
        uint32_t sW = sb + bAddrW0 + (uint32_t)((ic & 1) * WBUF * 2);
#pragma unroll
        for (int ks = 0; ks < 8; ks++) {
            uint32_t a[4][4], b[2][4];
#pragma unroll
            for (int mt = 0; mt < 4; mt++)
                ldsm4(a[mt][0], a[mt][1], a[mt][2], a[mt][3],
                      aAddrB + (uint32_t)((mt * 16 * STH + ks * 16) * 2));
#pragma unroll
            for (int pr = 0; pr < 2; pr++)
                ldsm4(b[pr][0], b[pr][1], b[pr][2], b[pr][3],
                      sW + (uint32_t)((pr * 16 * STH + ks * 16) * 2));
#pragma unroll
            for (int mt = 0; mt < 4; mt++)
#pragma unroll
                for (int nt = 0; nt < 4; nt++)
                    mma16816(outAcc[mt][nt], a[mt],
                             b[nt >> 1][(nt & 1) * 2], b[nt >> 1][(nt & 1) * 2 + 1]);
        }
    }
    __syncthreads();

    // ---- epilogue: stage f32 in B region (stride 132), coalesced writes ----
    {
        int rB = lane >> 2, nB = (lane & 3) * 2;
#pragma unroll
        for (int mt = 0; mt < 4; mt++) {
            int p = wmB * 64 + mt * 16 + rB;
#pragma unroll
            for (int nt = 0; nt < 4; nt++) {
                int nc = wnB * 32 + nt * 8 + nB;
                *(float2*)&smf[p * 132 + nc] =
                    make_float2(outAcc[mt][nt][0], outAcc[mt][nt][1]);
                *(float2*)&smf[(p + 8) * 132 + nc] =
                    make_float2(outAcc[mt][nt][2], outAcc[mt][nt][3]);
            }
        }
    }
    __syncthreads();

#pragma unroll
    for (int it = 0; it < 16; it++) {
        int f = it * 256 + tid;          // 4096 float4
        int p = f >> 5;                  // pair 0..127 (= lloc*8+mloc)
        int c4 = (f & 31) * 4;
        int l = bl * 16 + (p >> 3);
        int m = bm * 8 + (p & 7);
        size_t o = ((size_t)(l * L_ + m)) * DP + c4;
        float4 v = *(float4*)&smf[p * 132 + c4];
        float4 pv = *(const float4*)&pairin[o];
        float4 bv = *(const float4*)&bo[c4];
        v.x += pv.x + bv.x; v.y += pv.y + bv.y;
        v.z += pv.z + bv.z; v.w += pv.w + bv.w;
        *(float4*)&outp[o] = v;
    }
}

// ---------------------------------------------------------------------------
// Launch
// ---------------------------------------------------------------------------
extern "C" void kernel_launch(void* const* d_in, const int* in_sizes, int n_in,
                              void* d_out, int out_size)
{
    const float* msa    = (const float*)d_in[0];
    const float* pairin = (const float*)d_in[1];
    const float* gamma  = (const float*)d_in[4];
    const float* beta   = (const float*)d_in[5];
    const float* wl     = (const float*)d_in[6];
    const float* bleft  = (const float*)d_in[7];
    const float* wr     = (const float*)d_in[8];
    const float* bright = (const float*)d_in[9];
    const float* wo     = (const float*)d_in[10];
    const float* bo     = (const float*)d_in[11];
    float* outp = (float*)d_out;

    int smemLn = 192 * XST * 2;
    cudaFuncSetAttribute(ln_proj_kernel,
                         cudaFuncAttributeMaxDynamicSharedMemorySize, smemLn);
    cudaFuncSetAttribute(fused_gemm_kernel,
                         cudaFuncAttributeMaxDynamicSharedMemorySize, SMEM_FUSED);

    ln_proj_kernel<<<256, 256, smemLn>>>(msa, gamma, beta, wl, bleft, wr, bright);
    wt_kernel<<<512, 256>>>(wo);
    fused_gemm_kernel<<<dim3(16, 32), 256, SMEM_FUSED>>>(pairin, bo, outp);
}